// round 16
// baseline (speedup 1.0000x reference)
#include <cuda_runtime.h>
#include <cuda_bf16.h>

#define N_NODES 50000
#define E_EDGES 600000
#define EHALF   (E_EDGES / 2)
#define EQUART  (E_EDGES / 4)
#define FDIM    128
#define HDIM    16

// device state — referenced ONLY inside device code.
// Self-cleaning invariant: consumer phases reset what they consume (replay-safe).
__device__ int          g_mode;
__device__ float        g_deg  [N_NODES];        // 0 at rest
__device__ float        g_dinv [N_NODES];
__device__ unsigned int g_hb   [N_NODES * 8];    // bf16x2-packed h1s, then z1s
__device__ unsigned int g_acc1b[N_NODES * 8];    // bf16x2 accum, 0 at rest
__device__ unsigned int g_acc2b[N_NODES * 8];    // bf16x2 accum, 0 at rest

__device__ __forceinline__ int load_edge_idx(const unsigned int* __restrict__ ei,
                                             int mode, int pos) {
    if (mode == 1) return (int)ei[2 * pos];             // int64: low word
    unsigned int v = ei[pos];
    if (mode == 2) return (int)__int_as_float((int)v);  // float32-encoded
    return (int)v;                                      // int32
}

__device__ __forceinline__ unsigned int pack_bf2(float lo, float hi) {
    __nv_bfloat162 t = __floats2bfloat162_rn(lo, hi);
    return *(unsigned int*)&t;
}
__device__ __forceinline__ float2 unpack_bf2(unsigned int v) {
    __nv_bfloat162 t = *(__nv_bfloat162*)&v;
    return make_float2(__low2float(t), __high2float(t));
}

// 8 bf16 adds in one L2 atomic op (sm_90+)
__device__ __forceinline__ void red_add_bf16x2_v4(unsigned int* addr, uint4 v) {
    asm volatile("red.global.add.noftz.v4.bf16x2 [%0], {%1,%2,%3,%4};"
                 :: "l"(addr), "r"(v.x), "r"(v.y), "r"(v.z), "r"(v.w) : "memory");
}

// per-block edge-dtype sniff from the first 256 words (1 KB)
__device__ __forceinline__ int detect_mode_block(const unsigned int* __restrict__ ei) {
    __shared__ int s_big, s_odd;
    if (threadIdx.x == 0) { s_big = 0; s_odd = 0; }
    __syncthreads();
    if (threadIdx.x < 256) {
        unsigned int v = ei[threadIdx.x];
        if (v >= 0x30000000u)              atomicAdd(&s_big, 1);
        if ((threadIdx.x & 1) && v != 0u)  atomicAdd(&s_odd, 1);
    }
    __syncthreads();
    return (s_big > 64) ? 2 : ((s_odd == 0) ? 1 : 0);
}

// ---- launch 0: detect (per block) + degree count, 2 edges/thread ----
__global__ void deg_kernel(const unsigned int* __restrict__ ei) {
    int mode = detect_mode_block(ei);
    if (blockIdx.x == 0 && threadIdx.x == 0)
        g_mode = mode;                      // published for later launches

    int e0 = blockIdx.x * blockDim.x + threadIdx.x;
    if (e0 >= EHALF) return;
    int c0 = load_edge_idx(ei, mode, E_EDGES + e0);
    int c1 = load_edge_idx(ei, mode, E_EDGES + e0 + EHALF);
    if ((unsigned)c0 < (unsigned)N_NODES) atomicAdd(&g_deg[c0], 1.0f);
    if ((unsigned)c1 < (unsigned)N_NODES) atomicAdd(&g_deg[c1], 1.0f);
}

// ---- launch 1: h1s = dinv*(x@W1), bf16x2-packed; publish dinv; reset deg ----
__global__ void gemm1_kernel(const float* __restrict__ x, const float* __restrict__ W1) {
    __shared__ float sW1[FDIM * HDIM];
    for (int i = threadIdx.x; i < FDIM * HDIM; i += blockDim.x)
        sW1[i] = W1[i];
    __syncthreads();

    int gid = blockIdx.x * blockDim.x + threadIdx.x;
    int row = gid >> 2;
    int q   = gid & 3;
    int jg  = q * 4;
    if (row >= N_NODES) return;

    float dinv = rsqrtf(g_deg[row] + 1.0f);   // +1 = self-loop

    const float4* xr = (const float4*)(x + (size_t)row * FDIM);
    float4 acc = make_float4(0.f, 0.f, 0.f, 0.f);
#pragma unroll
    for (int k4 = 0; k4 < FDIM / 4; k4++) {
        float4 xv = xr[k4];
        float4 w0 = *(const float4*)&sW1[(k4 * 4 + 0) * HDIM + jg];
        float4 w1 = *(const float4*)&sW1[(k4 * 4 + 1) * HDIM + jg];
        float4 w2 = *(const float4*)&sW1[(k4 * 4 + 2) * HDIM + jg];
        float4 w3 = *(const float4*)&sW1[(k4 * 4 + 3) * HDIM + jg];
        acc.x += xv.x * w0.x + xv.y * w1.x + xv.z * w2.x + xv.w * w3.x;
        acc.y += xv.x * w0.y + xv.y * w1.y + xv.z * w2.y + xv.w * w3.y;
        acc.z += xv.x * w0.z + xv.y * w1.z + xv.z * w2.z + xv.w * w3.z;
        acc.w += xv.x * w0.w + xv.y * w1.w + xv.z * w2.w + xv.w * w3.w;
    }
    uint2 packed;
    packed.x = pack_bf2(acc.x * dinv, acc.y * dinv);
    packed.y = pack_bf2(acc.z * dinv, acc.w * dinv);
    *(uint2*)(g_hb + row * 8 + q * 2) = packed;

    if (q == 0) {
        g_dinv[row] = dinv;
        g_deg[row]  = 0.0f;    // self-clean for next replay
    }
}

// ---- launches 2 & 4: aggregation, 4 edges/thread for deep MLP ----
template <int PASS>
__global__ void agg_kernel(const unsigned int* __restrict__ ei) {
    int e0 = blockIdx.x * blockDim.x + threadIdx.x;
    if (e0 >= EQUART) return;

    unsigned int* __restrict__ acc = (PASS == 0) ? g_acc1b : g_acc2b;
    int mode = g_mode;

    int r[4], c[4];
    bool ok[4];
#pragma unroll
    for (int i = 0; i < 4; i++) {
        int e = e0 + i * EQUART;
        r[i] = load_edge_idx(ei, mode, e);
        c[i] = load_edge_idx(ei, mode, E_EDGES + e);
        ok[i] = (unsigned)r[i] < (unsigned)N_NODES && (unsigned)c[i] < (unsigned)N_NODES;
    }

    // issue all gathers before any RED (independent loads → MLP 8)
    uint4 lo[4], hi[4];
#pragma unroll
    for (int i = 0; i < 4; i++) {
        if (ok[i]) {
            const uint4* h = (const uint4*)(g_hb + r[i] * 8);
            lo[i] = h[0]; hi[i] = h[1];
        }
    }
#pragma unroll
    for (int i = 0; i < 4; i++) {
        if (ok[i]) {
            unsigned int* ac = acc + c[i] * 8;
            red_add_bf16x2_v4(ac,     lo[i]);
            red_add_bf16x2_v4(ac + 4, hi[i]);
        }
    }
}

// ---- launch 3: z1s = dinv*relu(dinv*(acc1+h1s)+b1); reset acc1 — uint4 ----
__global__ void relu_bias_kernel(const float* __restrict__ b1) {
    int idx = blockIdx.x * blockDim.x + threadIdx.x;   // N_NODES*2 threads
    if (idx >= N_NODES * 2) return;
    int node = idx >> 1;
    int half = idx & 1;                                 // features [half*8, half*8+8)

    float dinv = g_dinv[node];
    uint4 av4 = *(const uint4*)(g_acc1b + node * 8 + half * 4);
    uint4 hv4 = *(const uint4*)(g_hb    + node * 8 + half * 4);
    float4 bA = ((const float4*)b1)[half * 2 + 0];
    float4 bB = ((const float4*)b1)[half * 2 + 1];

    uint4 z4;
    {
        float2 a = unpack_bf2(av4.x), h = unpack_bf2(hv4.x);
        z4.x = pack_bf2(fmaxf(dinv * (a.x + h.x) + bA.x, 0.f) * dinv,
                        fmaxf(dinv * (a.y + h.y) + bA.y, 0.f) * dinv);
    }
    {
        float2 a = unpack_bf2(av4.y), h = unpack_bf2(hv4.y);
        z4.y = pack_bf2(fmaxf(dinv * (a.x + h.x) + bA.z, 0.f) * dinv,
                        fmaxf(dinv * (a.y + h.y) + bA.w, 0.f) * dinv);
    }
    {
        float2 a = unpack_bf2(av4.z), h = unpack_bf2(hv4.z);
        z4.z = pack_bf2(fmaxf(dinv * (a.x + h.x) + bB.x, 0.f) * dinv,
                        fmaxf(dinv * (a.y + h.y) + bB.y, 0.f) * dinv);
    }
    {
        float2 a = unpack_bf2(av4.w), h = unpack_bf2(hv4.w);
        z4.w = pack_bf2(fmaxf(dinv * (a.x + h.x) + bB.z, 0.f) * dinv,
                        fmaxf(dinv * (a.y + h.y) + bB.w, 0.f) * dinv);
    }
    *(uint4*)(g_hb    + node * 8 + half * 4) = z4;
    *(uint4*)(g_acc1b + node * 8 + half * 4) = make_uint4(0u, 0u, 0u, 0u);  // self-clean
}

// ---- launch 5: out = log_softmax(dinv*(acc2+z1s) @ W2 + b2); reset acc2 ----
__global__ void final_kernel(const float* __restrict__ W2, const float* __restrict__ b2,
                             float* __restrict__ out) {
    __shared__ float sW2[HDIM * FDIM];
    __shared__ float sb2[FDIM];
    for (int i = threadIdx.x; i < HDIM * FDIM; i += blockDim.x) sW2[i] = W2[i];
    for (int i = threadIdx.x; i < FDIM; i += blockDim.x)        sb2[i] = b2[i];
    __syncthreads();

    int warp = (blockIdx.x * blockDim.x + threadIdx.x) >> 5;
    int lane = threadIdx.x & 31;
    if (warp >= N_NODES) return;

    float dinv = g_dinv[warp];
    float a[HDIM];
#pragma unroll
    for (int t = 0; t < 8; t++) {
        float2 av = unpack_bf2(g_acc2b[warp * 8 + t]);
        float2 hv = unpack_bf2(g_hb   [warp * 8 + t]);
        a[2 * t + 0] = dinv * (av.x + hv.x);
        a[2 * t + 1] = dinv * (av.y + hv.y);
    }
    if (lane < 2)
        *(uint4*)(g_acc2b + warp * 8 + lane * 4) = make_uint4(0u, 0u, 0u, 0u);

    int c0 = lane * 4;
    float o0 = sb2[c0 + 0], o1 = sb2[c0 + 1], o2 = sb2[c0 + 2], o3 = sb2[c0 + 3];
#pragma unroll
    for (int k = 0; k < HDIM; k++) {
        float4 w = *(const float4*)&sW2[k * FDIM + c0];
        o0 += a[k] * w.x; o1 += a[k] * w.y; o2 += a[k] * w.z; o3 += a[k] * w.w;
    }

    float m = fmaxf(fmaxf(o0, o1), fmaxf(o2, o3));
#pragma unroll
    for (int off = 16; off > 0; off >>= 1)
        m = fmaxf(m, __shfl_xor_sync(0xFFFFFFFFu, m, off));

    float s = expf(o0 - m) + expf(o1 - m) + expf(o2 - m) + expf(o3 - m);
#pragma unroll
    for (int off = 16; off > 0; off >>= 1)
        s += __shfl_xor_sync(0xFFFFFFFFu, s, off);
    float lse = m + logf(s);

    float4 r = make_float4(o0 - lse, o1 - lse, o2 - lse, o3 - lse);
    *(float4*)(out + (size_t)warp * FDIM + c0) = r;
}

extern "C" void kernel_launch(void* const* d_in, const int* in_sizes, int n_in,
                              void* d_out, int out_size) {
    const float*        x  = nullptr;
    const unsigned int* ei = nullptr;
    const float*        W1 = nullptr;
    const float*        W2 = nullptr;
    const float*        b1 = nullptr;
    const float*        b2 = nullptr;

    for (int i = 0; i < n_in; i++) {
        long long sz = in_sizes[i];
        if (sz == 6400000LL || sz == 25600000LL)        x  = (const float*)d_in[i];
        else if (sz == 1200000LL || sz == 2400000LL ||
                 sz == 4800000LL || sz == 9600000LL)     ei = (const unsigned int*)d_in[i];
        else if (sz == 2048LL || sz == 8192LL) { if (!W1) W1 = (const float*)d_in[i];
                                                 else     W2 = (const float*)d_in[i]; }
        else if (sz == 16LL  || sz == 64LL)              b1 = (const float*)d_in[i];
        else if (sz == 128LL || sz == 512LL)             b2 = (const float*)d_in[i];
    }
    if (!x)  x  = (const float*)d_in[0];
    if (!ei) ei = (const unsigned int*)d_in[1];
    if (!W1) W1 = (const float*)d_in[2];
    if (!b1) b1 = (const float*)d_in[3];
    if (!W2) W2 = (const float*)d_in[4];
    if (!b2) b2 = (const float*)d_in[5];

    float* out = (float*)d_out;
    const int T = 256;

    deg_kernel<<<(EHALF + T - 1) / T, T>>>(ei);                     // 0 (detect fused)
    gemm1_kernel<<<(N_NODES * 4 + T - 1) / T, T>>>(x, W1);          // 1
    agg_kernel<0><<<(EQUART + T - 1) / T, T>>>(ei);                 // 2
    relu_bias_kernel<<<(N_NODES * 2 + T - 1) / T, T>>>(b1);         // 3
    agg_kernel<1><<<(EQUART + T - 1) / T, T>>>(ei);                 // 4
    final_kernel<<<(N_NODES * 32 + T - 1) / T, T>>>(W2, b2, out);   // 5  <- ncu -s 5
}

// round 17
// speedup vs baseline: 1.1314x; 1.1314x over previous
#include <cuda_runtime.h>
#include <cuda_bf16.h>

#define N_NODES 50000
#define E_EDGES 600000
#define EHALF   (E_EDGES / 2)
#define FDIM    128
#define HDIM    16

// device state — referenced ONLY inside device code.
// Self-cleaning invariant: consumer phases reset what they consume (replay-safe).
__device__ int          g_mode;
__device__ float        g_deg  [N_NODES];        // 0 at rest
__device__ float        g_dinv [N_NODES];
__device__ unsigned int g_hb   [N_NODES * 8];    // bf16x2-packed h1s, then z1s
__device__ unsigned int g_acc1b[N_NODES * 8];    // bf16x2 accum, 0 at rest
__device__ unsigned int g_acc2b[N_NODES * 8];    // bf16x2 accum, 0 at rest

#if defined(__CUDA_ARCH__) && (__CUDA_ARCH__ >= 900)
#define GRID_DEP_SYNC()  cudaGridDependencySynchronize()
#define GRID_TRIGGER()   cudaTriggerProgrammaticLaunchCompletion()
#else
#define GRID_DEP_SYNC()
#define GRID_TRIGGER()
#endif

__device__ __forceinline__ int load_edge_idx(const unsigned int* __restrict__ ei,
                                             int mode, int pos) {
    if (mode == 1) return (int)ei[2 * pos];             // int64: low word
    unsigned int v = ei[pos];
    if (mode == 2) return (int)__int_as_float((int)v);  // float32-encoded
    return (int)v;                                      // int32
}

__device__ __forceinline__ unsigned int pack_bf2(float lo, float hi) {
    __nv_bfloat162 t = __floats2bfloat162_rn(lo, hi);
    return *(unsigned int*)&t;
}
__device__ __forceinline__ float2 unpack_bf2(unsigned int v) {
    __nv_bfloat162 t = *(__nv_bfloat162*)&v;
    return make_float2(__low2float(t), __high2float(t));
}

// 8 bf16 adds in one L2 atomic op (sm_90+)
__device__ __forceinline__ void red_add_bf16x2_v4(unsigned int* addr, uint4 v) {
    asm volatile("red.global.add.noftz.v4.bf16x2 [%0], {%1,%2,%3,%4};"
                 :: "l"(addr), "r"(v.x), "r"(v.y), "r"(v.z), "r"(v.w) : "memory");
}

// per-block edge-dtype sniff from the first 256 words (1 KB)
__device__ __forceinline__ int detect_mode_block(const unsigned int* __restrict__ ei) {
    __shared__ int s_big, s_odd;
    if (threadIdx.x == 0) { s_big = 0; s_odd = 0; }
    __syncthreads();
    if (threadIdx.x < 256) {
        unsigned int v = ei[threadIdx.x];
        if (v >= 0x30000000u)              atomicAdd(&s_big, 1);
        if ((threadIdx.x & 1) && v != 0u)  atomicAdd(&s_odd, 1);
    }
    __syncthreads();
    return (s_big > 64) ? 2 : ((s_odd == 0) ? 1 : 0);
}

// ---- launch 0: detect + degree count. Triggers IMMEDIATELY so gemm's
//      (deg-independent) matmul overlaps the atomic storm. ----
__global__ void deg_kernel(const unsigned int* __restrict__ ei) {
    GRID_TRIGGER();                         // let gemm start computing x@W1 now

    int mode = detect_mode_block(ei);
    if (blockIdx.x == 0 && threadIdx.x == 0)
        g_mode = mode;

    int e0 = blockIdx.x * blockDim.x + threadIdx.x;
    if (e0 >= EHALF) return;
    int c0 = load_edge_idx(ei, mode, E_EDGES + e0);
    int c1 = load_edge_idx(ei, mode, E_EDGES + e0 + EHALF);
    if ((unsigned)c0 < (unsigned)N_NODES) atomicAdd(&g_deg[c0], 1.0f);
    if ((unsigned)c1 < (unsigned)N_NODES) atomicAdd(&g_deg[c1], 1.0f);
}

// ---- launch 1: h1s = dinv*(x@W1). ENTIRE matmul runs pre-sync (x, W1 are
//      inputs); only the dinv scale + store waits on deg. ----
__global__ void gemm1_kernel(const float* __restrict__ x, const float* __restrict__ W1) {
    __shared__ float sW1[FDIM * HDIM];
    for (int i = threadIdx.x; i < FDIM * HDIM; i += blockDim.x)
        sW1[i] = W1[i];
    __syncthreads();

    int gid = blockIdx.x * blockDim.x + threadIdx.x;
    int row = gid >> 2;
    int q   = gid & 3;
    int jg  = q * 4;

    float4 acc = make_float4(0.f, 0.f, 0.f, 0.f);
    if (row < N_NODES) {
        const float4* xr = (const float4*)(x + (size_t)row * FDIM);
#pragma unroll
        for (int k4 = 0; k4 < FDIM / 4; k4++) {
            float4 xv = xr[k4];
            float4 w0 = *(const float4*)&sW1[(k4 * 4 + 0) * HDIM + jg];
            float4 w1 = *(const float4*)&sW1[(k4 * 4 + 1) * HDIM + jg];
            float4 w2 = *(const float4*)&sW1[(k4 * 4 + 2) * HDIM + jg];
            float4 w3 = *(const float4*)&sW1[(k4 * 4 + 3) * HDIM + jg];
            acc.x += xv.x * w0.x + xv.y * w1.x + xv.z * w2.x + xv.w * w3.x;
            acc.y += xv.x * w0.y + xv.y * w1.y + xv.z * w2.y + xv.w * w3.y;
            acc.z += xv.x * w0.z + xv.y * w1.z + xv.z * w2.z + xv.w * w3.z;
            acc.w += xv.x * w0.w + xv.y * w1.w + xv.z * w2.w + xv.w * w3.w;
        }
    }

    GRID_DEP_SYNC();                        // wait for deg counts

    if (row < N_NODES) {
        float dinv = rsqrtf(g_deg[row] + 1.0f);   // +1 = self-loop
        uint2 packed;
        packed.x = pack_bf2(acc.x * dinv, acc.y * dinv);
        packed.y = pack_bf2(acc.z * dinv, acc.w * dinv);
        *(uint2*)(g_hb + row * 8 + q * 2) = packed;
        if (q == 0) {
            g_dinv[row] = dinv;
            g_deg[row]  = 0.0f;             // self-clean for next replay
        }
    }
    GRID_TRIGGER();
}

// ---- launches 2 & 4: aggregation, 2 edges/thread; index loads pre-sync ----
template <int PASS>
__global__ void agg_kernel(const unsigned int* __restrict__ ei) {
    int e0 = blockIdx.x * blockDim.x + threadIdx.x;

    unsigned int* __restrict__ acc = (PASS == 0) ? g_acc1b : g_acc2b;

    int r0 = 0, c0 = 0, r1 = 0, c1 = 0;
    bool ok0 = false, ok1 = false;
    if (e0 < EHALF) {
        int mode = g_mode;                  // set by deg (2 launches back) — safe
        int e1 = e0 + EHALF;
        r0 = load_edge_idx(ei, mode, e0);
        c0 = load_edge_idx(ei, mode, E_EDGES + e0);
        r1 = load_edge_idx(ei, mode, e1);
        c1 = load_edge_idx(ei, mode, E_EDGES + e1);
        ok0 = (unsigned)r0 < (unsigned)N_NODES && (unsigned)c0 < (unsigned)N_NODES;
        ok1 = (unsigned)r1 < (unsigned)N_NODES && (unsigned)c1 < (unsigned)N_NODES;
    }

    GRID_DEP_SYNC();                        // wait for g_hb (and acc reset)

    uint4 lo0, hi0, lo1, hi1;
    if (ok0) { const uint4* h = (const uint4*)(g_hb + r0 * 8); lo0 = h[0]; hi0 = h[1]; }
    if (ok1) { const uint4* h = (const uint4*)(g_hb + r1 * 8); lo1 = h[0]; hi1 = h[1]; }
    if (ok0) {
        unsigned int* ac = acc + c0 * 8;
        red_add_bf16x2_v4(ac,     lo0);
        red_add_bf16x2_v4(ac + 4, hi0);
    }
    if (ok1) {
        unsigned int* ac = acc + c1 * 8;
        red_add_bf16x2_v4(ac,     lo1);
        red_add_bf16x2_v4(ac + 4, hi1);
    }
    GRID_TRIGGER();
}

// ---- launch 3: z1s = dinv*relu(dinv*(acc1+h1s)+b1); reset acc1 — uint4 ----
__global__ void relu_bias_kernel(const float* __restrict__ b1) {
    int idx = blockIdx.x * blockDim.x + threadIdx.x;   // N_NODES*2 threads
    int node = idx >> 1;
    int half = idx & 1;
    float4 bA = ((const float4*)b1)[half * 2 + 0];     // input — pre-sync OK
    float4 bB = ((const float4*)b1)[half * 2 + 1];

    GRID_DEP_SYNC();                        // wait for agg<0>

    if (idx < N_NODES * 2) {
        float dinv = g_dinv[node];
        uint4 av4 = *(const uint4*)(g_acc1b + node * 8 + half * 4);
        uint4 hv4 = *(const uint4*)(g_hb    + node * 8 + half * 4);
        uint4 z4;
        {
            float2 a = unpack_bf2(av4.x), h = unpack_bf2(hv4.x);
            z4.x = pack_bf2(fmaxf(dinv * (a.x + h.x) + bA.x, 0.f) * dinv,
                            fmaxf(dinv * (a.y + h.y) + bA.y, 0.f) * dinv);
        }
        {
            float2 a = unpack_bf2(av4.y), h = unpack_bf2(hv4.y);
            z4.y = pack_bf2(fmaxf(dinv * (a.x + h.x) + bA.z, 0.f) * dinv,
                            fmaxf(dinv * (a.y + h.y) + bA.w, 0.f) * dinv);
        }
        {
            float2 a = unpack_bf2(av4.z), h = unpack_bf2(hv4.z);
            z4.z = pack_bf2(fmaxf(dinv * (a.x + h.x) + bB.x, 0.f) * dinv,
                            fmaxf(dinv * (a.y + h.y) + bB.y, 0.f) * dinv);
        }
        {
            float2 a = unpack_bf2(av4.w), h = unpack_bf2(hv4.w);
            z4.w = pack_bf2(fmaxf(dinv * (a.x + h.x) + bB.z, 0.f) * dinv,
                            fmaxf(dinv * (a.y + h.y) + bB.w, 0.f) * dinv);
        }
        *(uint4*)(g_hb    + node * 8 + half * 4) = z4;
        *(uint4*)(g_acc1b + node * 8 + half * 4) = make_uint4(0u, 0u, 0u, 0u);
    }
    GRID_TRIGGER();
}

// ---- launch 5: out = log_softmax(dinv*(acc2+z1s) @ W2 + b2); reset acc2 ----
__global__ void final_kernel(const float* __restrict__ W2, const float* __restrict__ b2,
                             float* __restrict__ out) {
    __shared__ float sW2[HDIM * FDIM];
    __shared__ float sb2[FDIM];
    for (int i = threadIdx.x; i < HDIM * FDIM; i += blockDim.x) sW2[i] = W2[i];
    for (int i = threadIdx.x; i < FDIM; i += blockDim.x)        sb2[i] = b2[i];
    __syncthreads();                        // inputs — pre-sync OK

    GRID_DEP_SYNC();                        // wait for agg<1>

    int warp = (blockIdx.x * blockDim.x + threadIdx.x) >> 5;
    int lane = threadIdx.x & 31;
    if (warp >= N_NODES) return;

    float dinv = g_dinv[warp];
    float a[HDIM];
#pragma unroll
    for (int t = 0; t < 8; t++) {
        float2 av = unpack_bf2(g_acc2b[warp * 8 + t]);
        float2 hv = unpack_bf2(g_hb   [warp * 8 + t]);
        a[2 * t + 0] = dinv * (av.x + hv.x);
        a[2 * t + 1] = dinv * (av.y + hv.y);
    }
    if (lane < 2)
        *(uint4*)(g_acc2b + warp * 8 + lane * 4) = make_uint4(0u, 0u, 0u, 0u);

    int c0 = lane * 4;
    float o0 = sb2[c0 + 0], o1 = sb2[c0 + 1], o2 = sb2[c0 + 2], o3 = sb2[c0 + 3];
#pragma unroll
    for (int k = 0; k < HDIM; k++) {
        float4 w = *(const float4*)&sW2[k * FDIM + c0];
        o0 += a[k] * w.x; o1 += a[k] * w.y; o2 += a[k] * w.z; o3 += a[k] * w.w;
    }

    float m = fmaxf(fmaxf(o0, o1), fmaxf(o2, o3));
#pragma unroll
    for (int off = 16; off > 0; off >>= 1)
        m = fmaxf(m, __shfl_xor_sync(0xFFFFFFFFu, m, off));

    float s = expf(o0 - m) + expf(o1 - m) + expf(o2 - m) + expf(o3 - m);
#pragma unroll
    for (int off = 16; off > 0; off >>= 1)
        s += __shfl_xor_sync(0xFFFFFFFFu, s, off);
    float lse = m + logf(s);

    float4 r = make_float4(o0 - lse, o1 - lse, o2 - lse, o3 - lse);
    *(float4*)(out + (size_t)warp * FDIM + c0) = r;
}

// helper: launch with PDL attribute, fall back to plain launch on error
template <typename K, typename... Args>
static void launch_pdl(K kernel, int grid, int block, Args... args) {
    cudaLaunchConfig_t cfg = {};
    cfg.gridDim  = dim3(grid, 1, 1);
    cfg.blockDim = dim3(block, 1, 1);
    cfg.stream   = 0;
    cudaLaunchAttribute attr;
    attr.id = cudaLaunchAttributeProgrammaticStreamSerialization;
    attr.val.programmaticStreamSerializationAllowed = 1;
    cfg.attrs = &attr;
    cfg.numAttrs = 1;
    if (cudaLaunchKernelEx(&cfg, kernel, args...) != cudaSuccess) {
        cudaGetLastError();                 // clear; fall back (sync becomes no-op wait)
        kernel<<<grid, block>>>(args...);
    }
}

extern "C" void kernel_launch(void* const* d_in, const int* in_sizes, int n_in,
                              void* d_out, int out_size) {
    const float*        x  = nullptr;
    const unsigned int* ei = nullptr;
    const float*        W1 = nullptr;
    const float*        W2 = nullptr;
    const float*        b1 = nullptr;
    const float*        b2 = nullptr;

    for (int i = 0; i < n_in; i++) {
        long long sz = in_sizes[i];
        if (sz == 6400000LL || sz == 25600000LL)        x  = (const float*)d_in[i];
        else if (sz == 1200000LL || sz == 2400000LL ||
                 sz == 4800000LL || sz == 9600000LL)     ei = (const unsigned int*)d_in[i];
        else if (sz == 2048LL || sz == 8192LL) { if (!W1) W1 = (const float*)d_in[i];
                                                 else     W2 = (const float*)d_in[i]; }
        else if (sz == 16LL  || sz == 64LL)              b1 = (const float*)d_in[i];
        else if (sz == 128LL || sz == 512LL)             b2 = (const float*)d_in[i];
    }
    if (!x)  x  = (const float*)d_in[0];
    if (!ei) ei = (const unsigned int*)d_in[1];
    if (!W1) W1 = (const float*)d_in[2];
    if (!b1) b1 = (const float*)d_in[3];
    if (!W2) W2 = (const float*)d_in[4];
    if (!b2) b2 = (const float*)d_in[5];

    float* out = (float*)d_out;
    const int T = 256;

    deg_kernel<<<(EHALF + T - 1) / T, T>>>(ei);                          // 0 (plain)
    launch_pdl(gemm1_kernel,     (N_NODES * 4 + T - 1) / T, T, x, W1);   // 1
    launch_pdl(agg_kernel<0>,    (EHALF + T - 1) / T, T, ei);            // 2
    launch_pdl(relu_bias_kernel, (N_NODES * 2 + T - 1) / T, T, b1);      // 3
    launch_pdl(agg_kernel<1>,    (EHALF + T - 1) / T, T, ei);            // 4
    launch_pdl(final_kernel,     (N_NODES * 32 + T - 1) / T, T, W2, b2, out);  // 5
}